// round 2
// baseline (speedup 1.0000x reference)
#include <cuda_runtime.h>
#include <cstdint>

#define K_DIM 4096
#define N_DIM 8192
#define INFCAP 100.0f
#define BP_EPS 1e-4f

// ---------------- scratch (no allocation allowed) ----------------
__device__ float g_colsum[N_DIM];   // sum_k Hxs[k,n]
__device__ float g_colsum2[N_DIM];  // sum_k Hxs_new[k,n]
__device__ float g_prior[N_DIM];    // clip(dope+phi+colsum, +-INFCAP)
__device__ float g_dope[N_DIM];     // doping LLR

__device__ __forceinline__ float tanh_approx(float x) {
    float r;
    asm("tanh.approx.f32 %0, %1;" : "=f"(r) : "f"(x));
    return r;
}

// ---------------- K0: zero accumulators ----------------
__global__ void k_zero() {
    int i = blockIdx.x * blockDim.x + threadIdx.x;
    if (i < N_DIM) { g_colsum[i] = 0.f; g_colsum2[i] = 0.f; }
}

// ---------------- K1/K3: column sums (coalesced, float4, per-block partial + atomic) ----
// grid = (N/1024, K/64), block = 256. Each thread: 4 columns x 64 rows.
__global__ __launch_bounds__(256) void k_colsum(const float* __restrict__ M, int which) {
    float* acc = which ? g_colsum2 : g_colsum;
    const int ROWS = 64;
    int cbase = blockIdx.x * 1024 + threadIdx.x * 4;
    int r0 = blockIdx.y * ROWS;
    const float4* p = (const float4*)(M + (size_t)r0 * N_DIM + cbase);
    float4 a = make_float4(0.f, 0.f, 0.f, 0.f);
#pragma unroll 8
    for (int r = 0; r < ROWS; r++) {
        float4 v = p[(size_t)r * (N_DIM / 4)];
        a.x += v.x; a.y += v.y; a.z += v.z; a.w += v.w;
    }
    atomicAdd(&acc[cbase + 0], a.x);
    atomicAdd(&acc[cbase + 1], a.y);
    atomicAdd(&acc[cbase + 2], a.z);
    atomicAdd(&acc[cbase + 3], a.w);
}

// ---------------- K1b: dope / phi / prior ----------------
__global__ void k_prior(const float* __restrict__ ps, const float* __restrict__ Min) {
    int n = blockIdx.x * blockDim.x + threadIdx.x;
    if (n >= N_DIM) return;
    float p0 = ps[2 * n], p1 = ps[2 * n + 1];
    float pn = p1 / (p0 + p1);
    float dope = logf(1.f - pn) - logf(pn);
    float m0 = Min[2 * n], m1 = Min[2 * n + 1];
    float mn = m1 / (m0 + m1);
    float phi = logf(1.f - mn) - logf(mn);
    g_dope[n] = dope;
    float pr = dope + phi + g_colsum[n];
    g_prior[n] = fminf(fmaxf(pr, -INFCAP), INFCAP);
}

// ---------------- K2: main row kernel ----------------
// One CTA per check row k. Row tanhm kept in SMEM (32KB) so the leave-one-out
// second sweep does no DRAM reads.
__device__ __forceinline__ float bp_elem(float t, float prod, float s) {
    if (t == 0.f) return 0.f;                        // zero-mask -> arctanh(0) -> 0
    float y = s * __fdividef(prod, t);               // (1-2x) * prodtanhm / tanhm
    y = fminf(fmaxf(y, -1.f), 1.f);
    float r = __logf(__fdividef(1.f + y, 1.f - y));  // 2*atanh(y); +-inf at endpoints
    return fminf(fmaxf(r, -1.f), 1.f);               // clip absorbs inf
}

__global__ __launch_bounds__(512) void k_main(const float* __restrict__ Hxs,
                                              const int* __restrict__ H,
                                              const int* __restrict__ x,
                                              float* __restrict__ out_Hxs) {
    __shared__ float t_sm[N_DIM];
    __shared__ float warp_prod[16];
    int k = blockIdx.x;
    int tid = threadIdx.x;
    float s = (float)(1 - 2 * x[k]);

    const float4* hx4 = (const float4*)(Hxs + (size_t)k * N_DIM);
    const int4*   h4  = (const int4*)(H + (size_t)k * N_DIM);
    const float4* pr4 = (const float4*)g_prior;
    float4* tsm4 = (float4*)t_sm;

    float p = 1.f;
#pragma unroll
    for (int i = 0; i < 4; i++) {
        int idx = tid + i * 512;
        float4 hx = hx4[idx];
        int4   h  = h4[idx];
        float4 pr = pr4[idx];
        float4 t;
        t.x = tanh_approx(0.5f * (h.x ? (pr.x + BP_EPS - hx.x) : -hx.x));
        t.y = tanh_approx(0.5f * (h.y ? (pr.y + BP_EPS - hx.y) : -hx.y));
        t.z = tanh_approx(0.5f * (h.z ? (pr.z + BP_EPS - hx.z) : -hx.z));
        t.w = tanh_approx(0.5f * (h.w ? (pr.w + BP_EPS - hx.w) : -hx.w));
        float mx = (t.x == 0.f) ? 1.f : t.x;
        float my = (t.y == 0.f) ? 1.f : t.y;
        float mz = (t.z == 0.f) ? 1.f : t.z;
        float mw = (t.w == 0.f) ? 1.f : t.w;
        p *= mx * my * mz * mw;
        tsm4[idx] = t;
    }

    // block product reduction (16 warps)
#pragma unroll
    for (int off = 16; off; off >>= 1) p *= __shfl_xor_sync(0xffffffffu, p, off);
    if ((tid & 31) == 0) warp_prod[tid >> 5] = p;
    __syncthreads();
    if (tid < 16) {
        float q = warp_prod[tid];
#pragma unroll
        for (int off = 8; off; off >>= 1) q *= __shfl_xor_sync(0x0000ffffu, q, off);
        if (tid == 0) warp_prod[0] = q;
    }
    __syncthreads();
    float prod = warp_prod[0];

    float4* o4 = (float4*)(out_Hxs + (size_t)k * N_DIM);
#pragma unroll
    for (int i = 0; i < 4; i++) {
        int idx = tid + i * 512;
        float4 t = tsm4[idx];
        float4 o;
        o.x = bp_elem(t.x, prod, s);
        o.y = bp_elem(t.y, prod, s);
        o.z = bp_elem(t.z, prod, s);
        o.w = bp_elem(t.w, prod, s);
        o4[idx] = o;
    }
}

// ---------------- K3b: output beliefs ----------------
__global__ void k_out(float* __restrict__ out_M) {
    int n = blockIdx.x * blockDim.x + threadIdx.x;
    if (n >= N_DIM) return;
    float z = (1.f - tanhf((g_colsum2[n] + g_dope[n]) * 0.5f)) * 0.5f;
    out_M[2 * n + 0] = 1.f - z;
    out_M[2 * n + 1] = z;
}

extern "C" void kernel_launch(void* const* d_in, const int* in_sizes, int n_in,
                              void* d_out, int out_size) {
    const float* ps  = (const float*)d_in[0];
    const float* Min = (const float*)d_in[1];
    const float* Hxs = (const float*)d_in[2];
    const int*   x   = (const int*)d_in[3];
    const int*   H   = (const int*)d_in[4];

    float* out     = (float*)d_out;
    float* out_M   = out;                 // M_out [N,2] first
    float* out_Hxs = out + 2 * N_DIM;     // Hxs_new [K,N] second

    k_zero<<<N_DIM / 256, 256>>>();
    k_colsum<<<dim3(N_DIM / 1024, K_DIM / 64), 256>>>(Hxs, 0);
    k_prior<<<N_DIM / 256, 256>>>(ps, Min);
    k_main<<<K_DIM, 512>>>(Hxs, H, x, out_Hxs);
    k_colsum<<<dim3(N_DIM / 1024, K_DIM / 64), 256>>>(out_Hxs, 1);
    k_out<<<N_DIM / 256, 256>>>(out_M);
}

// round 3
// speedup vs baseline: 1.0005x; 1.0005x over previous
#include <cuda_runtime.h>
#include <cstdint>

#define K_DIM 4096
#define N_DIM 8192
#define INFCAP 100.0f
#define BP_EPS 1e-4f

// ---------------- scratch (no allocation allowed) ----------------
__device__ float g_colsum[N_DIM];   // sum_k Hxs[k,n]
__device__ float g_colsum2[N_DIM];  // sum_k Hxs_new[k,n]
__device__ float g_prior[N_DIM];    // clip(dope+phi+colsum, +-INFCAP)
__device__ float g_dope[N_DIM];     // doping LLR

__device__ __forceinline__ float tanh_approx(float x) {
    float r;
    asm("tanh.approx.f32 %0, %1;" : "=f"(r) : "f"(x));
    return r;
}

// ---------------- K0: zero accumulators ----------------
__global__ void k_zero() {
    int i = blockIdx.x * blockDim.x + threadIdx.x;
    if (i < N_DIM) { g_colsum[i] = 0.f; g_colsum2[i] = 0.f; }
}

// ---------------- K1/K3: column sums (coalesced, float4, per-block partial + atomic) ----
// grid = (N/1024, K/64), block = 256. Each thread: 4 columns x 64 rows.
__global__ __launch_bounds__(256) void k_colsum(const float* __restrict__ M, int which) {
    float* acc = which ? g_colsum2 : g_colsum;
    const int ROWS = 64;
    int cbase = blockIdx.x * 1024 + threadIdx.x * 4;
    int r0 = blockIdx.y * ROWS;
    const float4* p = (const float4*)(M + (size_t)r0 * N_DIM + cbase);
    float4 a = make_float4(0.f, 0.f, 0.f, 0.f);
#pragma unroll 8
    for (int r = 0; r < ROWS; r++) {
        float4 v = p[(size_t)r * (N_DIM / 4)];
        a.x += v.x; a.y += v.y; a.z += v.z; a.w += v.w;
    }
    atomicAdd(&acc[cbase + 0], a.x);
    atomicAdd(&acc[cbase + 1], a.y);
    atomicAdd(&acc[cbase + 2], a.z);
    atomicAdd(&acc[cbase + 3], a.w);
}

// ---------------- K1b: dope / phi / prior ----------------
__global__ void k_prior(const float* __restrict__ ps, const float* __restrict__ Min) {
    int n = blockIdx.x * blockDim.x + threadIdx.x;
    if (n >= N_DIM) return;
    float p0 = ps[2 * n], p1 = ps[2 * n + 1];
    float pn = p1 / (p0 + p1);
    float dope = logf(1.f - pn) - logf(pn);
    float m0 = Min[2 * n], m1 = Min[2 * n + 1];
    float mn = m1 / (m0 + m1);
    float phi = logf(1.f - mn) - logf(mn);
    g_dope[n] = dope;
    float pr = dope + phi + g_colsum[n];
    g_prior[n] = fminf(fmaxf(pr, -INFCAP), INFCAP);
}

// ---------------- K2: main row kernel ----------------
// One CTA per check row k. Row tanhm kept in SMEM (32KB) so the leave-one-out
// second sweep does no DRAM reads.
__device__ __forceinline__ float bp_elem(float t, float prod, float s) {
    if (t == 0.f) return 0.f;                        // zero-mask -> arctanh(0) -> 0
    float y = s * __fdividef(prod, t);               // (1-2x) * prodtanhm / tanhm
    y = fminf(fmaxf(y, -1.f), 1.f);
    float r = __logf(__fdividef(1.f + y, 1.f - y));  // 2*atanh(y); +-inf at endpoints
    return fminf(fmaxf(r, -1.f), 1.f);               // clip absorbs inf
}

__global__ __launch_bounds__(512) void k_main(const float* __restrict__ Hxs,
                                              const int* __restrict__ H,
                                              const int* __restrict__ x,
                                              float* __restrict__ out_Hxs) {
    __shared__ float t_sm[N_DIM];
    __shared__ float warp_prod[16];
    int k = blockIdx.x;
    int tid = threadIdx.x;
    float s = (float)(1 - 2 * x[k]);

    const float4* hx4 = (const float4*)(Hxs + (size_t)k * N_DIM);
    const int4*   h4  = (const int4*)(H + (size_t)k * N_DIM);
    const float4* pr4 = (const float4*)g_prior;
    float4* tsm4 = (float4*)t_sm;

    float p = 1.f;
#pragma unroll
    for (int i = 0; i < 4; i++) {
        int idx = tid + i * 512;
        float4 hx = hx4[idx];
        int4   h  = h4[idx];
        float4 pr = pr4[idx];
        float4 t;
        t.x = tanh_approx(0.5f * (h.x ? (pr.x + BP_EPS - hx.x) : -hx.x));
        t.y = tanh_approx(0.5f * (h.y ? (pr.y + BP_EPS - hx.y) : -hx.y));
        t.z = tanh_approx(0.5f * (h.z ? (pr.z + BP_EPS - hx.z) : -hx.z));
        t.w = tanh_approx(0.5f * (h.w ? (pr.w + BP_EPS - hx.w) : -hx.w));
        float mx = (t.x == 0.f) ? 1.f : t.x;
        float my = (t.y == 0.f) ? 1.f : t.y;
        float mz = (t.z == 0.f) ? 1.f : t.z;
        float mw = (t.w == 0.f) ? 1.f : t.w;
        p *= mx * my * mz * mw;
        tsm4[idx] = t;
    }

    // block product reduction (16 warps)
#pragma unroll
    for (int off = 16; off; off >>= 1) p *= __shfl_xor_sync(0xffffffffu, p, off);
    if ((tid & 31) == 0) warp_prod[tid >> 5] = p;
    __syncthreads();
    if (tid < 16) {
        float q = warp_prod[tid];
#pragma unroll
        for (int off = 8; off; off >>= 1) q *= __shfl_xor_sync(0x0000ffffu, q, off);
        if (tid == 0) warp_prod[0] = q;
    }
    __syncthreads();
    float prod = warp_prod[0];

    float4* o4 = (float4*)(out_Hxs + (size_t)k * N_DIM);
#pragma unroll
    for (int i = 0; i < 4; i++) {
        int idx = tid + i * 512;
        float4 t = tsm4[idx];
        float4 o;
        o.x = bp_elem(t.x, prod, s);
        o.y = bp_elem(t.y, prod, s);
        o.z = bp_elem(t.z, prod, s);
        o.w = bp_elem(t.w, prod, s);
        o4[idx] = o;
    }
}

// ---------------- K3b: output beliefs ----------------
__global__ void k_out(float* __restrict__ out_M) {
    int n = blockIdx.x * blockDim.x + threadIdx.x;
    if (n >= N_DIM) return;
    float z = (1.f - tanhf((g_colsum2[n] + g_dope[n]) * 0.5f)) * 0.5f;
    out_M[2 * n + 0] = 1.f - z;
    out_M[2 * n + 1] = z;
}

extern "C" void kernel_launch(void* const* d_in, const int* in_sizes, int n_in,
                              void* d_out, int out_size) {
    const float* ps  = (const float*)d_in[0];
    const float* Min = (const float*)d_in[1];
    const float* Hxs = (const float*)d_in[2];
    const int*   x   = (const int*)d_in[3];
    const int*   H   = (const int*)d_in[4];

    float* out     = (float*)d_out;
    float* out_M   = out;                 // M_out [N,2] first
    float* out_Hxs = out + 2 * N_DIM;     // Hxs_new [K,N] second

    k_zero<<<N_DIM / 256, 256>>>();
    k_colsum<<<dim3(N_DIM / 1024, K_DIM / 64), 256>>>(Hxs, 0);
    k_prior<<<N_DIM / 256, 256>>>(ps, Min);
    k_main<<<K_DIM, 512>>>(Hxs, H, x, out_Hxs);
    k_colsum<<<dim3(N_DIM / 1024, K_DIM / 64), 256>>>(out_Hxs, 1);
    k_out<<<N_DIM / 256, 256>>>(out_M);
}